// round 4
// baseline (speedup 1.0000x reference)
#include <cuda_runtime.h>
#include <math.h>

#define N 8192
#define N4 (N / 4)

// ---- pass1 tiling: 64x64 ----
#define T1 64
#define NB1 (N / T1)                      // 128
#define NPAIRS1 (NB1 * (NB1 + 1) / 2)     // 8256

// ---- pass2 tiling: 32x32 ----
#define T2 32
#define NB2 (N / T2)                      // 256
#define NPAIRS2 (NB2 * (NB2 + 1) / 2)     // 32896

__device__ float g_rowsum[N];

template <int NB>
__device__ __forceinline__ int pair_offset(int bi) {
    return bi * NB - (bi * (bi - 1)) / 2;
}

template <int NB>
__device__ __forceinline__ void decode_pair(int p, int& bi, int& bj) {
    float disc = (float)((2 * NB + 1) * (2 * NB + 1) - 8 * p);
    int b = (int)(((float)(2 * NB + 1) - sqrtf(disc)) * 0.5f);
    if (b < 0) b = 0;
    if (b > NB - 1) b = NB - 1;
    while (b + 1 <= NB - 1 && pair_offset<NB>(b + 1) <= p) b++;
    while (b > 0 && pair_offset<NB>(b) > p) b--;
    bi = b;
    bj = bi + (p - pair_offset<NB>(b));
}

__global__ void init_rowsum_kernel() {
    int i = blockIdx.x * blockDim.x + threadIdx.x;
    if (i < N) g_rowsum[i] = 1.0f;   // self-loop pre-added
}

// Pass 1: rowsum[i] += sum_j max(adj[i,j], adj[j,i]).  64x64 tile pairs.
__global__ __launch_bounds__(256) void pass1_kernel(const float4* __restrict__ adj4) {
    int bi, bj;
    decode_pair<NB1>(blockIdx.x, bi, bj);
    const int r0 = bi * T1;
    const int c0 = bj * T1;

    const int t    = threadIdx.x;
    const int q    = t & 15;     // float4 column 0..15
    const int rr   = t >> 4;     // row group 0..15
    const int lane = t & 31;
    const int wid  = t >> 5;

    __shared__ float Bs[T1][T1 + 1];
    __shared__ float Cs[8][T1];

    float4 a[4], b[4];
    #pragma unroll
    for (int k = 0; k < 4; k++) {
        int row = rr + 16 * k;
        a[k] = adj4[(size_t)(r0 + row) * N4 + (c0 >> 2) + q];
        b[k] = adj4[(size_t)(c0 + row) * N4 + (r0 >> 2) + q];
    }
    #pragma unroll
    for (int k = 0; k < 4; k++) {
        int row = rr + 16 * k;
        Bs[row][4 * q + 0] = b[k].x;
        Bs[row][4 * q + 1] = b[k].y;
        Bs[row][4 * q + 2] = b[k].z;
        Bs[row][4 * q + 3] = b[k].w;
    }
    __syncthreads();

    float cx = 0.0f, cy = 0.0f, cz = 0.0f, cw = 0.0f;
    #pragma unroll
    for (int k = 0; k < 4; k++) {
        int row = rr + 16 * k;
        float4 m;
        m.x = fmaxf(a[k].x, Bs[4 * q + 0][row]);
        m.y = fmaxf(a[k].y, Bs[4 * q + 1][row]);
        m.z = fmaxf(a[k].z, Bs[4 * q + 2][row]);
        m.w = fmaxf(a[k].w, Bs[4 * q + 3][row]);

        float rs = (m.x + m.y) + (m.z + m.w);
        rs += __shfl_down_sync(0xffffffffu, rs, 8, 16);
        rs += __shfl_down_sync(0xffffffffu, rs, 4, 16);
        rs += __shfl_down_sync(0xffffffffu, rs, 2, 16);
        rs += __shfl_down_sync(0xffffffffu, rs, 1, 16);
        if (q == 0) atomicAdd(&g_rowsum[r0 + row], rs);

        cx += m.x; cy += m.y; cz += m.z; cw += m.w;
    }

    if (bi != bj) {
        cx += __shfl_xor_sync(0xffffffffu, cx, 16);
        cy += __shfl_xor_sync(0xffffffffu, cy, 16);
        cz += __shfl_xor_sync(0xffffffffu, cz, 16);
        cw += __shfl_xor_sync(0xffffffffu, cw, 16);
        if (lane < 16) {
            Cs[wid][4 * q + 0] = cx;
            Cs[wid][4 * q + 1] = cy;
            Cs[wid][4 * q + 2] = cz;
            Cs[wid][4 * q + 3] = cw;
        }
        __syncthreads();
        if (t < T1) {
            float s = 0.0f;
            #pragma unroll
            for (int w = 0; w < 8; w++) s += Cs[w][t];
            atomicAdd(&g_rowsum[c0 + t], s);
        }
    }
}

// Pass 2: out[i,j] = d[i]*d[j]*(max(adj[i,j],adj[j,i]) + (i==j)).  32x32 tiles,
// dinv computed inline via rsqrtf(rowsum) (rowsum loads hit L2; MUFU is idle).
__global__ __launch_bounds__(256) void pass2_kernel(const float4* __restrict__ adj4,
                                                    float4* __restrict__ out4) {
    int bi, bj;
    decode_pair<NB2>(NPAIRS2 - 1 - (int)blockIdx.x, bi, bj);
    const int r0 = bi * T2;
    const int c0 = bj * T2;

    const int t   = threadIdx.x;
    const int row = t >> 3;      // 0..31
    const int q   = t & 7;       // 0..7

    __shared__ float Bs[T2][T2 + 1];
    __shared__ float Ms[T2][T2 + 1];

    float4 a = adj4[(size_t)(r0 + row) * N4 + (c0 >> 2) + q];
    float4 b = adj4[(size_t)(c0 + row) * N4 + (r0 >> 2) + q];

    Bs[row][4 * q + 0] = b.x;
    Bs[row][4 * q + 1] = b.y;
    Bs[row][4 * q + 2] = b.z;
    Bs[row][4 * q + 3] = b.w;
    __syncthreads();

    float4 m;
    m.x = fmaxf(a.x, Bs[4 * q + 0][row]);
    m.y = fmaxf(a.y, Bs[4 * q + 1][row]);
    m.z = fmaxf(a.z, Bs[4 * q + 2][row]);
    m.w = fmaxf(a.w, Bs[4 * q + 3][row]);

    if (bi == bj) {
        if (4 * q + 0 == row) m.x += 1.0f;
        if (4 * q + 1 == row) m.y += 1.0f;
        if (4 * q + 2 == row) m.z += 1.0f;
        if (4 * q + 3 == row) m.w += 1.0f;
    }

    // inline D^-1/2
    const float rsi = g_rowsum[r0 + row];
    const float di  = (rsi > 0.0f) ? rsqrtf(rsi) : 0.0f;
    const float4 rj4 = ((const float4*)g_rowsum)[(c0 >> 2) + q];
    float4 dj4;
    dj4.x = (rj4.x > 0.0f) ? rsqrtf(rj4.x) : 0.0f;
    dj4.y = (rj4.y > 0.0f) ? rsqrtf(rj4.y) : 0.0f;
    dj4.z = (rj4.z > 0.0f) ? rsqrtf(rj4.z) : 0.0f;
    dj4.w = (rj4.w > 0.0f) ? rsqrtf(rj4.w) : 0.0f;

    float4 v;
    v.x = di * dj4.x * m.x;
    v.y = di * dj4.y * m.y;
    v.z = di * dj4.z * m.z;
    v.w = di * dj4.w * m.w;

    out4[(size_t)(r0 + row) * N4 + (c0 >> 2) + q] = v;

    if (bi != bj) {
        Ms[row][4 * q + 0] = v.x;
        Ms[row][4 * q + 1] = v.y;
        Ms[row][4 * q + 2] = v.z;
        Ms[row][4 * q + 3] = v.w;
        __syncthreads();

        float4 tr;
        tr.x = Ms[4 * q + 0][row];
        tr.y = Ms[4 * q + 1][row];
        tr.z = Ms[4 * q + 2][row];
        tr.w = Ms[4 * q + 3][row];
        out4[(size_t)(c0 + row) * N4 + (r0 >> 2) + q] = tr;
    }
}

extern "C" void kernel_launch(void* const* d_in, const int* in_sizes, int n_in,
                              void* d_out, int out_size) {
    const float4* adj4 = (const float4*)d_in[0];
    float4* out4 = (float4*)d_out;

    init_rowsum_kernel<<<(N + 255) / 256, 256>>>();
    pass1_kernel<<<NPAIRS1, 256>>>(adj4);
    pass2_kernel<<<NPAIRS2, 256>>>(adj4, out4);
}

// round 5
// speedup vs baseline: 1.0593x; 1.0593x over previous
#include <cuda_runtime.h>
#include <math.h>

#define N 8192
#define N4 (N / 4)

// ---- pass1 tiling: 64x64 ----
#define T1 64
#define NB1 (N / T1)                      // 128
#define NPAIRS1 (NB1 * (NB1 + 1) / 2)     // 8256

// ---- pass2 tiling: 32x32 ----
#define T2 32
#define NB2 (N / T2)                      // 256
#define NPAIRS2 (NB2 * (NB2 + 1) / 2)     // 32896

__device__ float g_rowsum[N];

template <int NB>
__device__ __forceinline__ int pair_offset(int bi) {
    return bi * NB - (bi * (bi - 1)) / 2;
}

template <int NB>
__device__ __forceinline__ void decode_pair(int p, int& bi, int& bj) {
    float disc = (float)((2 * NB + 1) * (2 * NB + 1) - 8 * p);
    int b = (int)(((float)(2 * NB + 1) - sqrtf(disc)) * 0.5f);
    if (b < 0) b = 0;
    if (b > NB - 1) b = NB - 1;
    while (b + 1 <= NB - 1 && pair_offset<NB>(b + 1) <= p) b++;
    while (b > 0 && pair_offset<NB>(b) > p) b--;
    bi = b;
    bj = bi + (p - pair_offset<NB>(b));
}

// Pass 1: rowsum[i] = sum_j max(adj[i,j], adj[j,i]) + (self loop on diag blocks).
// 64x64 tile pairs; adj reads use default caching so the tail stays L2-resident
// for pass2's (reverse-ordered) reads.
__global__ __launch_bounds__(256) void pass1_kernel(const float4* __restrict__ adj4) {
    int bi, bj;
    decode_pair<NB1>(blockIdx.x, bi, bj);
    const int r0 = bi * T1;
    const int c0 = bj * T1;

    const int t    = threadIdx.x;
    const int q    = t & 15;     // float4 column 0..15
    const int rr   = t >> 4;     // row group 0..15
    const int lane = t & 31;
    const int wid  = t >> 5;

    __shared__ float Bs[T1][T1 + 1];
    __shared__ float Cs[8][T1];

    float4 a[4], b[4];
    #pragma unroll
    for (int k = 0; k < 4; k++) {
        int row = rr + 16 * k;
        a[k] = adj4[(size_t)(r0 + row) * N4 + (c0 >> 2) + q];
        b[k] = adj4[(size_t)(c0 + row) * N4 + (r0 >> 2) + q];
    }
    #pragma unroll
    for (int k = 0; k < 4; k++) {
        int row = rr + 16 * k;
        Bs[row][4 * q + 0] = b[k].x;
        Bs[row][4 * q + 1] = b[k].y;
        Bs[row][4 * q + 2] = b[k].z;
        Bs[row][4 * q + 3] = b[k].w;
    }
    __syncthreads();

    const bool diag = (bi == bj);
    float cx = 0.0f, cy = 0.0f, cz = 0.0f, cw = 0.0f;
    #pragma unroll
    for (int k = 0; k < 4; k++) {
        int row = rr + 16 * k;
        float4 m;
        m.x = fmaxf(a[k].x, Bs[4 * q + 0][row]);
        m.y = fmaxf(a[k].y, Bs[4 * q + 1][row]);
        m.z = fmaxf(a[k].z, Bs[4 * q + 2][row]);
        m.w = fmaxf(a[k].w, Bs[4 * q + 3][row]);
        if (diag) {   // self-loop
            if (4 * q + 0 == row) m.x += 1.0f;
            if (4 * q + 1 == row) m.y += 1.0f;
            if (4 * q + 2 == row) m.z += 1.0f;
            if (4 * q + 3 == row) m.w += 1.0f;
        }

        float rs = (m.x + m.y) + (m.z + m.w);
        rs += __shfl_down_sync(0xffffffffu, rs, 8, 16);
        rs += __shfl_down_sync(0xffffffffu, rs, 4, 16);
        rs += __shfl_down_sync(0xffffffffu, rs, 2, 16);
        rs += __shfl_down_sync(0xffffffffu, rs, 1, 16);
        if (q == 0) atomicAdd(&g_rowsum[r0 + row], rs);

        cx += m.x; cy += m.y; cz += m.z; cw += m.w;
    }

    if (!diag) {
        cx += __shfl_xor_sync(0xffffffffu, cx, 16);
        cy += __shfl_xor_sync(0xffffffffu, cy, 16);
        cz += __shfl_xor_sync(0xffffffffu, cz, 16);
        cw += __shfl_xor_sync(0xffffffffu, cw, 16);
        if (lane < 16) {
            Cs[wid][4 * q + 0] = cx;
            Cs[wid][4 * q + 1] = cy;
            Cs[wid][4 * q + 2] = cz;
            Cs[wid][4 * q + 3] = cw;
        }
        __syncthreads();
        if (t < T1) {
            float s = 0.0f;
            #pragma unroll
            for (int w = 0; w < 8; w++) s += Cs[w][t];
            atomicAdd(&g_rowsum[c0 + t], s);
        }
    }
}

// Pass 2: out[i,j] = d[i]*d[j]*(max(adj[i,j],adj[j,i]) + (i==j)).
// Reverse pair order + evict-first loads (__ldcs) + streaming stores (__stcs):
// the write stream and one-shot reads must not evict pass1's L2-resident tiles.
__global__ __launch_bounds__(256) void pass2_kernel(const float4* __restrict__ adj4,
                                                    float4* __restrict__ out4) {
    int bi, bj;
    decode_pair<NB2>(NPAIRS2 - 1 - (int)blockIdx.x, bi, bj);
    const int r0 = bi * T2;
    const int c0 = bj * T2;

    const int t   = threadIdx.x;
    const int row = t >> 3;      // 0..31
    const int q   = t & 7;       // 0..7

    __shared__ float Bs[T2][T2 + 1];
    __shared__ float Ms[T2][T2 + 1];

    float4 a = __ldcs(&adj4[(size_t)(r0 + row) * N4 + (c0 >> 2) + q]);
    float4 b = __ldcs(&adj4[(size_t)(c0 + row) * N4 + (r0 >> 2) + q]);

    Bs[row][4 * q + 0] = b.x;
    Bs[row][4 * q + 1] = b.y;
    Bs[row][4 * q + 2] = b.z;
    Bs[row][4 * q + 3] = b.w;
    __syncthreads();

    float4 m;
    m.x = fmaxf(a.x, Bs[4 * q + 0][row]);
    m.y = fmaxf(a.y, Bs[4 * q + 1][row]);
    m.z = fmaxf(a.z, Bs[4 * q + 2][row]);
    m.w = fmaxf(a.w, Bs[4 * q + 3][row]);

    if (bi == bj) {
        if (4 * q + 0 == row) m.x += 1.0f;
        if (4 * q + 1 == row) m.y += 1.0f;
        if (4 * q + 2 == row) m.z += 1.0f;
        if (4 * q + 3 == row) m.w += 1.0f;
    }

    // inline D^-1/2 (rowsum is tiny and L2-hot)
    const float rsi = g_rowsum[r0 + row];
    const float di  = (rsi > 0.0f) ? rsqrtf(rsi) : 0.0f;
    const float4 rj4 = ((const float4*)g_rowsum)[(c0 >> 2) + q];
    float4 dj4;
    dj4.x = (rj4.x > 0.0f) ? rsqrtf(rj4.x) : 0.0f;
    dj4.y = (rj4.y > 0.0f) ? rsqrtf(rj4.y) : 0.0f;
    dj4.z = (rj4.z > 0.0f) ? rsqrtf(rj4.z) : 0.0f;
    dj4.w = (rj4.w > 0.0f) ? rsqrtf(rj4.w) : 0.0f;

    float4 v;
    v.x = di * dj4.x * m.x;
    v.y = di * dj4.y * m.y;
    v.z = di * dj4.z * m.z;
    v.w = di * dj4.w * m.w;

    __stcs(&out4[(size_t)(r0 + row) * N4 + (c0 >> 2) + q], v);

    if (bi != bj) {
        Ms[row][4 * q + 0] = v.x;
        Ms[row][4 * q + 1] = v.y;
        Ms[row][4 * q + 2] = v.z;
        Ms[row][4 * q + 3] = v.w;
        __syncthreads();

        float4 tr;
        tr.x = Ms[4 * q + 0][row];
        tr.y = Ms[4 * q + 1][row];
        tr.z = Ms[4 * q + 2][row];
        tr.w = Ms[4 * q + 3][row];
        __stcs(&out4[(size_t)(c0 + row) * N4 + (r0 >> 2) + q], tr);
    }
}

extern "C" void kernel_launch(void* const* d_in, const int* in_sizes, int n_in,
                              void* d_out, int out_size) {
    const float4* adj4 = (const float4*)d_in[0];
    float4* out4 = (float4*)d_out;

    void* rowsum_ptr = nullptr;
    cudaGetSymbolAddress(&rowsum_ptr, g_rowsum);
    cudaMemsetAsync(rowsum_ptr, 0, N * sizeof(float));

    pass1_kernel<<<NPAIRS1, 256>>>(adj4);
    pass2_kernel<<<NPAIRS2, 256>>>(adj4, out4);
}